// round 1
// baseline (speedup 1.0000x reference)
#include <cuda_runtime.h>
#include <cstdint>

#define BB 2
#define TT 2048
#define HH 1024
#define NHH 16
#define HSS 64
#define MM (BB*TT)   // 4096

// ---------------- scratch (device globals; no allocation allowed) ----------
__device__ float g_Q[BB*NHH*TT*HSS];
__device__ float g_K[BB*NHH*TT*HSS];
__device__ float g_V[BB*NHH*TT*HSS];
__device__ float g_Y[BB*TT*HH];

// ---------------------------------------------------------------------------
// GEMM: C[M,1024] = A[M,1024] @ W[1024,1024]^T (+bias)
// MODE 0: plain store to out[m*1024+n]        (output projection)
// MODE 1: rope + scatter to [b,h,t,d]         (Q, K)
// MODE 2: scatter to [b,h,t,d], no rope       (V)
// Tiles: BM=128, BN=64, BK=16; 256 threads; 8x4 micro-tile.
// ---------------------------------------------------------------------------
template<int MODE>
__global__ void gemm_kernel(const float* __restrict__ A,
                            const float* __restrict__ W,
                            const float* __restrict__ bias,
                            const float* __restrict__ rope,
                            float* __restrict__ out)
{
    __shared__ alignas(16) float As[16*132];   // [k][m], stride 132 (pad)
    __shared__ alignas(16) float Bs[16*68];    // [k][n], stride 68  (pad)
    const int tid = threadIdx.x;
    const int tx = tid & 15, ty = tid >> 4;
    const int m0 = blockIdx.y * 128;
    const int n0 = blockIdx.x * 64;

    float acc[8][4];
    #pragma unroll
    for (int i = 0; i < 8; i++)
        #pragma unroll
        for (int j = 0; j < 4; j++) acc[i][j] = 0.f;

    for (int kt = 0; kt < 1024; kt += 16) {
        __syncthreads();
        // load A tile 128x16 (2 float4/thread), store transposed As[k][m]
        #pragma unroll
        for (int l = 0; l < 2; l++) {
            int e = l*256 + tid;          // 0..511
            int r = e >> 2, c4 = e & 3;
            float4 v = *(const float4*)(A + (size_t)(m0 + r)*1024 + kt + c4*4);
            As[(c4*4+0)*132 + r] = v.x;
            As[(c4*4+1)*132 + r] = v.y;
            As[(c4*4+2)*132 + r] = v.z;
            As[(c4*4+3)*132 + r] = v.w;
        }
        // load B tile 64x16 (1 float4/thread), store Bs[k][n]
        {
            int r = tid >> 2, c4 = tid & 3;
            float4 v = *(const float4*)(W + (size_t)(n0 + r)*1024 + kt + c4*4);
            Bs[(c4*4+0)*68 + r] = v.x;
            Bs[(c4*4+1)*68 + r] = v.y;
            Bs[(c4*4+2)*68 + r] = v.z;
            Bs[(c4*4+3)*68 + r] = v.w;
        }
        __syncthreads();
        #pragma unroll
        for (int k = 0; k < 16; k++) {
            const float4 a0 = *(const float4*)&As[k*132 + ty*8];
            const float4 a1 = *(const float4*)&As[k*132 + ty*8 + 4];
            const float4 b0 = *(const float4*)&Bs[k*68  + tx*4];
            float a[8] = {a0.x,a0.y,a0.z,a0.w,a1.x,a1.y,a1.z,a1.w};
            float bv[4] = {b0.x,b0.y,b0.z,b0.w};
            #pragma unroll
            for (int i = 0; i < 8; i++)
                #pragma unroll
                for (int j = 0; j < 4; j++)
                    acc[i][j] += a[i]*bv[j];
        }
    }

    // epilogue
    #pragma unroll
    for (int i = 0; i < 8; i++) {
        int m = m0 + ty*8 + i;
        int b = m / TT, t = m % TT;
        int ncol0 = n0 + tx*4;
        if (MODE != 0 && bias) {
            #pragma unroll
            for (int j = 0; j < 4; j++) acc[i][j] += bias[ncol0 + j];
        }
        if (MODE == 1) {
            int hd0 = ncol0 & 63;                 // aligned to 4 -> even
            #pragma unroll
            for (int p = 0; p < 2; p++) {
                int i0 = (hd0 >> 1) + p;          // rope pair index within head
                float cs = rope[((size_t)t*32 + i0)*2 + 0];
                float sn = rope[((size_t)t*32 + i0)*2 + 1];
                float xe = acc[i][2*p], xo = acc[i][2*p+1];
                acc[i][2*p]   = cs*xe - sn*xo;
                acc[i][2*p+1] = sn*xe + cs*xo;
            }
        }
        float4 o; o.x = acc[i][0]; o.y = acc[i][1]; o.z = acc[i][2]; o.w = acc[i][3];
        if (MODE == 0) {
            *(float4*)(out + (size_t)m*1024 + ncol0) = o;
        } else {
            int h = ncol0 >> 6, hd = ncol0 & 63;
            *(float4*)(out + (((size_t)(b*NHH + h))*TT + t)*HSS + hd) = o;
        }
    }
}

// ---------------------------------------------------------------------------
// Flash attention. grid = (T/64, B*NH), 256 threads.
// 64 q-rows/block; thread layout: row = tid>>2, sub = tid&3 (4 threads/row).
// Each thread owns k-columns kc = 4*c+sub (c=0..15) and a full acc[64].
// Masked / non-causal score = exactly -1e10 (matches reference semantics,
// including the fully-masked-row -> uniform-over-all-T degenerate case).
// ---------------------------------------------------------------------------
__global__ void attn_kernel(const float* __restrict__ Q,
                            const float* __restrict__ K,
                            const float* __restrict__ V,
                            const int* __restrict__ masks,
                            float* __restrict__ Y)
{
    extern __shared__ float smem[];
    float* Qs = smem;               // [64][68]
    float* Ks = smem + 64*68;       // [64][68]
    float* Vs = smem + 2*64*68;     // [64][68]
    __shared__ int mask_s[64];
    __shared__ int s_any;

    const int tid = threadIdx.x;
    const int bh = blockIdx.y;
    const int b  = bh >> 4;         // / NH
    const int h  = bh & 15;
    const int qt = blockIdx.x;
    const int q0 = qt * 64;
    const float* Qb = Q + (size_t)bh*TT*HSS;
    const float* Kb = K + (size_t)bh*TT*HSS;
    const float* Vb = V + (size_t)bh*TT*HSS;

    // load Q tile (64x64 floats = 1024 float4)
    #pragma unroll
    for (int l = 0; l < 4; l++) {
        int e = l*256 + tid;
        int r = e >> 4, d4 = e & 15;
        *(float4*)&Qs[r*68 + d4*4] =
            *(const float4*)(Qb + (size_t)(q0 + r)*HSS + d4*4);
    }

    const int row = tid >> 2;
    const int sub = tid & 3;
    const int qglob = q0 + row;

    float acc[64];
    #pragma unroll
    for (int d = 0; d < 64; d++) acc[d] = 0.f;
    float mrun = -3.0e38f;
    float lsum = 0.f;

    const int nkt = qt + 1;     // causal tiles
    for (int j = 0; j < nkt; j++) {
        __syncthreads();
        const int kbase = j*64;
        #pragma unroll
        for (int l = 0; l < 4; l++) {
            int e = l*256 + tid;
            int r = e >> 4, d4 = e & 15;
            *(float4*)&Ks[r*68 + d4*4] =
                *(const float4*)(Kb + (size_t)(kbase + r)*HSS + d4*4);
            *(float4*)&Vs[r*68 + d4*4] =
                *(const float4*)(Vb + (size_t)(kbase + r)*HSS + d4*4);
        }
        if (tid < 64) mask_s[tid] = masks[b*TT + kbase + tid];
        __syncthreads();

        // S = Q K^T for this thread's 16 columns
        float s[16];
        #pragma unroll
        for (int c = 0; c < 16; c++) s[c] = 0.f;
        #pragma unroll
        for (int d4 = 0; d4 < 16; d4++) {
            float4 q4 = *(const float4*)&Qs[row*68 + d4*4];
            #pragma unroll
            for (int c = 0; c < 16; c++) {
                int kc = 4*c + sub;
                float4 k4 = *(const float4*)&Ks[kc*68 + d4*4];
                s[c] += q4.x*k4.x + q4.y*k4.y + q4.z*k4.z + q4.w*k4.w;
            }
        }
        // scale + causal + pad mask (exact -1e10 like reference)
        #pragma unroll
        for (int c = 0; c < 16; c++) {
            int kc = 4*c + sub;
            int kg = kbase + kc;
            float val = s[c] * 0.125f;
            if (kg > qglob || mask_s[kc] != 0) val = -1e10f;
            s[c] = val;
        }
        // row max over 64 (16 local + shuffle across 4 subs)
        float mt = s[0];
        #pragma unroll
        for (int c = 1; c < 16; c++) mt = fmaxf(mt, s[c]);
        mt = fmaxf(mt, __shfl_xor_sync(0xffffffffu, mt, 1));
        mt = fmaxf(mt, __shfl_xor_sync(0xffffffffu, mt, 2));
        float mnew = fmaxf(mrun, mt);
        float corr = __expf(mrun - mnew);
        float psum = 0.f;
        #pragma unroll
        for (int c = 0; c < 16; c++) {
            float p = __expf(s[c] - mnew);
            s[c] = p;
            psum += p;
        }
        lsum = lsum*corr + psum;
        mrun = mnew;
        #pragma unroll
        for (int d = 0; d < 64; d++) acc[d] *= corr;
        // acc += P V (partial over this thread's 16 k's, full 64 dims)
        #pragma unroll
        for (int c = 0; c < 16; c++) {
            int kc = 4*c + sub;
            float p = s[c];
            #pragma unroll
            for (int d4 = 0; d4 < 16; d4++) {
                float4 v4 = *(const float4*)&Vs[kc*68 + d4*4];
                acc[d4*4+0] += p*v4.x;
                acc[d4*4+1] += p*v4.y;
                acc[d4*4+2] += p*v4.z;
                acc[d4*4+3] += p*v4.w;
            }
        }
    }

    // Degenerate rows: every entry of the full row equals -1e10 in the
    // reference -> uniform softmax over ALL T keys. Extend with future tiles.
    bool degen = (mrun < -0.9e10f);
    if (tid == 0) s_any = 0;
    __syncthreads();
    if (degen && sub == 0) s_any = 1;
    __syncthreads();
    if (s_any) {
        for (int j = nkt; j < TT/64; j++) {
            __syncthreads();
            #pragma unroll
            for (int l = 0; l < 4; l++) {
                int e = l*256 + tid;
                int r = e >> 4, d4 = e & 15;
                *(float4*)&Vs[r*68 + d4*4] =
                    *(const float4*)(Vb + (size_t)(j*64 + r)*HSS + d4*4);
            }
            __syncthreads();
            if (degen) {
                #pragma unroll
                for (int c = 0; c < 16; c++) {
                    int kc = 4*c + sub;
                    #pragma unroll
                    for (int d4 = 0; d4 < 16; d4++) {
                        float4 v4 = *(const float4*)&Vs[kc*68 + d4*4];
                        acc[d4*4+0] += v4.x;
                        acc[d4*4+1] += v4.y;
                        acc[d4*4+2] += v4.z;
                        acc[d4*4+3] += v4.w;
                    }
                }
                lsum += 16.f;
            }
        }
    }

    // reduce across the 4 subs of each row
    lsum += __shfl_xor_sync(0xffffffffu, lsum, 1);
    lsum += __shfl_xor_sync(0xffffffffu, lsum, 2);
    float inv = 1.0f / lsum;
    #pragma unroll
    for (int d = 0; d < 64; d++) {
        float v = acc[d];
        v += __shfl_xor_sync(0xffffffffu, v, 1);
        v += __shfl_xor_sync(0xffffffffu, v, 2);
        acc[d] = v * inv;
    }

    // store y in [B,T,H] layout (ready for output projection)
    int t = q0 + row;
    float* yp = Y + ((size_t)(b*TT + t))*HH + h*HSS;
    #pragma unroll
    for (int i = 0; i < 4; i++) {
        int d = sub*16 + i*4;
        float4 o; o.x = acc[d]; o.y = acc[d+1]; o.z = acc[d+2]; o.w = acc[d+3];
        *(float4*)(yp + d) = o;
    }
}

// ---------------------------------------------------------------------------
extern "C" void kernel_launch(void* const* d_in, const int* in_sizes, int n_in,
                              void* d_out, int out_size)
{
    const float* x     = (const float*)d_in[0];
    const int*   masks = (const int*)  d_in[1];
    const float* Wq    = (const float*)d_in[2];
    const float* bq    = (const float*)d_in[3];
    const float* Wk    = (const float*)d_in[4];
    const float* bk    = (const float*)d_in[5];
    const float* Wv    = (const float*)d_in[6];
    const float* bv    = (const float*)d_in[7];
    const float* Wo    = (const float*)d_in[8];
    const float* rope  = (const float*)d_in[9];
    float* out = (float*)d_out;

    float *Qp, *Kp, *Vp, *Yp;
    cudaGetSymbolAddress((void**)&Qp, g_Q);
    cudaGetSymbolAddress((void**)&Kp, g_K);
    cudaGetSymbolAddress((void**)&Vp, g_V);
    cudaGetSymbolAddress((void**)&Yp, g_Y);

    const int attn_smem = 3*64*68*(int)sizeof(float);   // 52224 B
    cudaFuncSetAttribute(attn_kernel,
                         cudaFuncAttributeMaxDynamicSharedMemorySize, attn_smem);

    dim3 gb(16, 32), tb(256);
    gemm_kernel<1><<<gb, tb>>>(x, Wq, bq, rope, Qp);
    gemm_kernel<1><<<gb, tb>>>(x, Wk, bk, rope, Kp);
    gemm_kernel<2><<<gb, tb>>>(x, Wv, bv, rope, Vp);

    attn_kernel<<<dim3(TT/64, BB*NHH), 256, attn_smem>>>(Qp, Kp, Vp, masks, Yp);

    gemm_kernel<0><<<gb, tb>>>(Yp, Wo, nullptr, nullptr, out);
}

// round 3
// speedup vs baseline: 1.3865x; 1.3865x over previous
#include <cuda_runtime.h>
#include <cstdint>

#define BB 2
#define TT 2048
#define HH 1024
#define NHH 16
#define HSS 64

// ---------------- scratch (device globals; no allocation allowed) ----------
__device__ float g_Q[BB*NHH*TT*HSS];
__device__ float g_K[BB*NHH*TT*HSS];
__device__ float g_V[BB*NHH*TT*HSS];
__device__ float g_Y[BB*TT*HH];

// ---------------------------------------------------------------------------
// tf32 helpers
// ---------------------------------------------------------------------------
__device__ __forceinline__ uint32_t f2tf32(float f) {
    uint32_t u;
    asm("cvt.rna.tf32.f32 %0, %1;" : "=r"(u) : "f"(f));
    return u;
}

__device__ __forceinline__ void mma_tf32(float c[4], const uint32_t a[4],
                                         const uint32_t b[2]) {
    asm volatile(
        "mma.sync.aligned.m16n8k8.row.col.f32.tf32.tf32.f32 "
        "{%0,%1,%2,%3}, {%4,%5,%6,%7}, {%8,%9}, {%0,%1,%2,%3};\n"
        : "+f"(c[0]), "+f"(c[1]), "+f"(c[2]), "+f"(c[3])
        : "r"(a[0]), "r"(a[1]), "r"(a[2]), "r"(a[3]),
          "r"(b[0]), "r"(b[1]));
}

// ---------------------------------------------------------------------------
// Tensor-core GEMM: C[M,1024] = A[M,1024] @ W[1024,1024]^T (+bias)
// MODE 0: plain store to out[m*1024+n]        (output projection)
// MODE 1: rope + scatter to [b,h,t,d]         (Q, K)
// MODE 2: scatter to [b,h,t,d], no rope       (V)
// Block 128x128x32, 8 warps (2x4), warp tile 64x32, m16n8k8 tf32 MMA.
// Shared stride 36 (pad 4) -> conflict-free fragment loads.
// ---------------------------------------------------------------------------
template<int MODE>
__global__ __launch_bounds__(256)
void gemm_tc(const float* __restrict__ A,
             const float* __restrict__ W,
             const float* __restrict__ bias,
             const float* __restrict__ rope,
             float* __restrict__ out)
{
    __shared__ alignas(16) uint32_t As[128*36];
    __shared__ alignas(16) uint32_t Bs[128*36];

    const int tid  = threadIdx.x;
    const int lane = tid & 31;
    const int w    = tid >> 5;
    const int g    = lane >> 2;     // 0..7
    const int t4   = lane & 3;      // 0..3
    const int wm   = w >> 2;        // 0..1 (M dir)
    const int wn   = w & 3;         // 0..3 (N dir)
    const int m0   = blockIdx.y * 128;
    const int n0   = blockIdx.x * 128;

    float c[4][4][4];
    #pragma unroll
    for (int im = 0; im < 4; im++)
        #pragma unroll
        for (int in = 0; in < 4; in++)
            #pragma unroll
            for (int q = 0; q < 4; q++) c[im][in][q] = 0.f;

    float4 ra[4], rb[4];

    // prologue: fetch tile 0
    #pragma unroll
    for (int l = 0; l < 4; l++) {
        int e = l*256 + tid, r = e >> 3, c4 = e & 7;
        ra[l] = *(const float4*)(A + (size_t)(m0 + r)*1024 + c4*4);
        rb[l] = *(const float4*)(W + (size_t)(n0 + r)*1024 + c4*4);
    }
    #pragma unroll
    for (int l = 0; l < 4; l++) {
        int e = l*256 + tid, r = e >> 3, c4 = e & 7;
        uint4 pa; pa.x = f2tf32(ra[l].x); pa.y = f2tf32(ra[l].y);
                  pa.z = f2tf32(ra[l].z); pa.w = f2tf32(ra[l].w);
        *(uint4*)&As[r*36 + c4*4] = pa;
        uint4 pb; pb.x = f2tf32(rb[l].x); pb.y = f2tf32(rb[l].y);
                  pb.z = f2tf32(rb[l].z); pb.w = f2tf32(rb[l].w);
        *(uint4*)&Bs[r*36 + c4*4] = pb;
    }
    __syncthreads();

    for (int kt = 0; kt < 1024; kt += 32) {
        const bool more = (kt + 32 < 1024);
        if (more) {
            #pragma unroll
            for (int l = 0; l < 4; l++) {
                int e = l*256 + tid, r = e >> 3, c4 = e & 7;
                ra[l] = *(const float4*)(A + (size_t)(m0 + r)*1024 + kt + 32 + c4*4);
                rb[l] = *(const float4*)(W + (size_t)(n0 + r)*1024 + kt + 32 + c4*4);
            }
        }
        // compute on current tile
        #pragma unroll
        for (int ks = 0; ks < 4; ks++) {
            uint32_t af[4][4], bf[4][2];
            const int kc = ks*8 + t4;
            #pragma unroll
            for (int im = 0; im < 4; im++) {
                int r0 = wm*64 + im*16 + g;
                af[im][0] = As[r0*36       + kc];
                af[im][1] = As[(r0+8)*36   + kc];
                af[im][2] = As[r0*36       + kc + 4];
                af[im][3] = As[(r0+8)*36   + kc + 4];
            }
            #pragma unroll
            for (int in = 0; in < 4; in++) {
                int n = wn*32 + in*8 + g;
                bf[in][0] = Bs[n*36 + kc];
                bf[in][1] = Bs[n*36 + kc + 4];
            }
            #pragma unroll
            for (int im = 0; im < 4; im++)
                #pragma unroll
                for (int in = 0; in < 4; in++)
                    mma_tf32(c[im][in], af[im], bf[in]);
        }
        if (more) {
            __syncthreads();
            #pragma unroll
            for (int l = 0; l < 4; l++) {
                int e = l*256 + tid, r = e >> 3, c4 = e & 7;
                uint4 pa; pa.x = f2tf32(ra[l].x); pa.y = f2tf32(ra[l].y);
                          pa.z = f2tf32(ra[l].z); pa.w = f2tf32(ra[l].w);
                *(uint4*)&As[r*36 + c4*4] = pa;
                uint4 pb; pb.x = f2tf32(rb[l].x); pb.y = f2tf32(rb[l].y);
                          pb.z = f2tf32(rb[l].z); pb.w = f2tf32(rb[l].w);
                *(uint4*)&Bs[r*36 + c4*4] = pb;
            }
            __syncthreads();
        }
    }

    // epilogue: c[im][in] layout -> c0:(g,2t) c1:(g,2t+1) c2:(g+8,2t) c3:(g+8,2t+1)
    #pragma unroll
    for (int im = 0; im < 4; im++) {
        #pragma unroll
        for (int rh = 0; rh < 2; rh++) {
            int m  = m0 + wm*64 + im*16 + g + rh*8;
            int b  = m >> 11;         // / TT
            int tt = m & 2047;        // % TT
            #pragma unroll
            for (int in = 0; in < 4; in++) {
                int n = n0 + wn*32 + in*8 + 2*t4;
                float v0 = c[im][in][rh*2 + 0];
                float v1 = c[im][in][rh*2 + 1];
                if (MODE != 0) { v0 += bias[n]; v1 += bias[n+1]; }
                if (MODE == 1) {
                    int i0 = (n & 63) >> 1;            // rope pair index
                    float cs = rope[((size_t)tt*32 + i0)*2 + 0];
                    float sn = rope[((size_t)tt*32 + i0)*2 + 1];
                    float nv0 = cs*v0 - sn*v1;
                    float nv1 = sn*v0 + cs*v1;
                    v0 = nv0; v1 = nv1;
                }
                if (MODE == 0) {
                    *(float2*)(out + (size_t)m*1024 + n) = make_float2(v0, v1);
                } else {
                    int h = n >> 6, hd = n & 63;
                    *(float2*)(out + (((size_t)(b*NHH + h))*TT + tt)*HSS + hd) =
                        make_float2(v0, v1);
                }
            }
        }
    }
}

// ---------------------------------------------------------------------------
// Flash attention (unchanged from R1 — known correct).
// ---------------------------------------------------------------------------
__global__ void attn_kernel(const float* __restrict__ Q,
                            const float* __restrict__ K,
                            const float* __restrict__ V,
                            const int* __restrict__ masks,
                            float* __restrict__ Y)
{
    extern __shared__ float smem[];
    float* Qs = smem;               // [64][68]
    float* Ks = smem + 64*68;       // [64][68]
    float* Vs = smem + 2*64*68;     // [64][68]
    __shared__ int mask_s[64];
    __shared__ int s_any;

    const int tid = threadIdx.x;
    const int bh = blockIdx.y;
    const int b  = bh >> 4;
    const int h  = bh & 15;
    const int qt = blockIdx.x;
    const int q0 = qt * 64;
    const float* Qb = Q + (size_t)bh*TT*HSS;
    const float* Kb = K + (size_t)bh*TT*HSS;
    const float* Vb = V + (size_t)bh*TT*HSS;

    #pragma unroll
    for (int l = 0; l < 4; l++) {
        int e = l*256 + tid;
        int r = e >> 4, d4 = e & 15;
        *(float4*)&Qs[r*68 + d4*4] =
            *(const float4*)(Qb + (size_t)(q0 + r)*HSS + d4*4);
    }

    const int row = tid >> 2;
    const int sub = tid & 3;
    const int qglob = q0 + row;

    float acc[64];
    #pragma unroll
    for (int d = 0; d < 64; d++) acc[d] = 0.f;
    float mrun = -3.0e38f;
    float lsum = 0.f;

    const int nkt = qt + 1;
    for (int j = 0; j < nkt; j++) {
        __syncthreads();
        const int kbase = j*64;
        #pragma unroll
        for (int l = 0; l < 4; l++) {
            int e = l*256 + tid;
            int r = e >> 4, d4 = e & 15;
            *(float4*)&Ks[r*68 + d4*4] =
                *(const float4*)(Kb + (size_t)(kbase + r)*HSS + d4*4);
            *(float4*)&Vs[r*68 + d4*4] =
                *(const float4*)(Vb + (size_t)(kbase + r)*HSS + d4*4);
        }
        if (tid < 64) mask_s[tid] = masks[b*TT + kbase + tid];
        __syncthreads();

        float s[16];
        #pragma unroll
        for (int cc = 0; cc < 16; cc++) s[cc] = 0.f;
        #pragma unroll
        for (int d4 = 0; d4 < 16; d4++) {
            float4 q4 = *(const float4*)&Qs[row*68 + d4*4];
            #pragma unroll
            for (int cc = 0; cc < 16; cc++) {
                int kc = 4*cc + sub;
                float4 k4 = *(const float4*)&Ks[kc*68 + d4*4];
                s[cc] += q4.x*k4.x + q4.y*k4.y + q4.z*k4.z + q4.w*k4.w;
            }
        }
        #pragma unroll
        for (int cc = 0; cc < 16; cc++) {
            int kc = 4*cc + sub;
            int kg = kbase + kc;
            float val = s[cc] * 0.125f;
            if (kg > qglob || mask_s[kc] != 0) val = -1e10f;
            s[cc] = val;
        }
        float mt = s[0];
        #pragma unroll
        for (int cc = 1; cc < 16; cc++) mt = fmaxf(mt, s[cc]);
        mt = fmaxf(mt, __shfl_xor_sync(0xffffffffu, mt, 1));
        mt = fmaxf(mt, __shfl_xor_sync(0xffffffffu, mt, 2));
        float mnew = fmaxf(mrun, mt);
        float corr = __expf(mrun - mnew);
        float psum = 0.f;
        #pragma unroll
        for (int cc = 0; cc < 16; cc++) {
            float p = __expf(s[cc] - mnew);
            s[cc] = p;
            psum += p;
        }
        lsum = lsum*corr + psum;
        mrun = mnew;
        #pragma unroll
        for (int d = 0; d < 64; d++) acc[d] *= corr;
        #pragma unroll
        for (int cc = 0; cc < 16; cc++) {
            int kc = 4*cc + sub;
            float p = s[cc];
            #pragma unroll
            for (int d4 = 0; d4 < 16; d4++) {
                float4 v4 = *(const float4*)&Vs[kc*68 + d4*4];
                acc[d4*4+0] += p*v4.x;
                acc[d4*4+1] += p*v4.y;
                acc[d4*4+2] += p*v4.z;
                acc[d4*4+3] += p*v4.w;
            }
        }
    }

    bool degen = (mrun < -0.9e10f);
    if (tid == 0) s_any = 0;
    __syncthreads();
    if (degen && sub == 0) s_any = 1;
    __syncthreads();
    if (s_any) {
        for (int j = nkt; j < TT/64; j++) {
            __syncthreads();
            #pragma unroll
            for (int l = 0; l < 4; l++) {
                int e = l*256 + tid;
                int r = e >> 4, d4 = e & 15;
                *(float4*)&Vs[r*68 + d4*4] =
                    *(const float4*)(Vb + (size_t)(j*64 + r)*HSS + d4*4);
            }
            __syncthreads();
            if (degen) {
                #pragma unroll
                for (int cc = 0; cc < 16; cc++) {
                    int kc = 4*cc + sub;
                    #pragma unroll
                    for (int d4 = 0; d4 < 16; d4++) {
                        float4 v4 = *(const float4*)&Vs[kc*68 + d4*4];
                        acc[d4*4+0] += v4.x;
                        acc[d4*4+1] += v4.y;
                        acc[d4*4+2] += v4.z;
                        acc[d4*4+3] += v4.w;
                    }
                }
                lsum += 16.f;
            }
        }
    }

    lsum += __shfl_xor_sync(0xffffffffu, lsum, 1);
    lsum += __shfl_xor_sync(0xffffffffu, lsum, 2);
    float inv = 1.0f / lsum;
    #pragma unroll
    for (int d = 0; d < 64; d++) {
        float v = acc[d];
        v += __shfl_xor_sync(0xffffffffu, v, 1);
        v += __shfl_xor_sync(0xffffffffu, v, 2);
        acc[d] = v * inv;
    }

    int t = q0 + row;
    float* yp = Y + ((size_t)(b*TT + t))*HH + h*HSS;
    #pragma unroll
    for (int i = 0; i < 4; i++) {
        int d = sub*16 + i*4;
        float4 o; o.x = acc[d]; o.y = acc[d+1]; o.z = acc[d+2]; o.w = acc[d+3];
        *(float4*)(yp + d) = o;
    }
}

// ---------------------------------------------------------------------------
extern "C" void kernel_launch(void* const* d_in, const int* in_sizes, int n_in,
                              void* d_out, int out_size)
{
    const float* x     = (const float*)d_in[0];
    const int*   masks = (const int*)  d_in[1];
    const float* Wq    = (const float*)d_in[2];
    const float* bq    = (const float*)d_in[3];
    const float* Wk    = (const float*)d_in[4];
    const float* bk    = (const float*)d_in[5];
    const float* Wv    = (const float*)d_in[6];
    const float* bv    = (const float*)d_in[7];
    const float* Wo    = (const float*)d_in[8];
    const float* rope  = (const float*)d_in[9];
    float* out = (float*)d_out;

    float *Qp, *Kp, *Vp, *Yp;
    cudaGetSymbolAddress((void**)&Qp, g_Q);
    cudaGetSymbolAddress((void**)&Kp, g_K);
    cudaGetSymbolAddress((void**)&Vp, g_V);
    cudaGetSymbolAddress((void**)&Yp, g_Y);

    const int attn_smem = 3*64*68*(int)sizeof(float);   // 52224 B
    cudaFuncSetAttribute(attn_kernel,
                         cudaFuncAttributeMaxDynamicSharedMemorySize, attn_smem);

    dim3 gb(8, 32), tb(256);
    gemm_tc<1><<<gb, tb>>>(x, Wq, bq, rope, Qp);
    gemm_tc<1><<<gb, tb>>>(x, Wk, bk, rope, Kp);
    gemm_tc<2><<<gb, tb>>>(x, Wv, bv, nullptr, Vp);

    attn_kernel<<<dim3(TT/64, BB*NHH), 256, attn_smem>>>(Qp, Kp, Vp, masks, Yp);

    gemm_tc<0><<<gb, tb>>>(Yp, Wo, nullptr, nullptr, out);
}

// round 4
// speedup vs baseline: 4.1676x; 3.0059x over previous
#include <cuda_runtime.h>
#include <cstdint>

#define BB 2
#define TT 2048
#define HH 1024
#define NHH 16
#define HSS 64

// ---------------- scratch (device globals; no allocation allowed) ----------
__device__ float g_Q[BB*NHH*TT*HSS];
__device__ float g_K[BB*NHH*TT*HSS];
__device__ float g_V[BB*NHH*TT*HSS];
__device__ float g_Y[BB*TT*HH];

// ---------------------------------------------------------------------------
// tf32 helpers
// ---------------------------------------------------------------------------
__device__ __forceinline__ uint32_t f2tf32(float f) {
    uint32_t u;
    asm("cvt.rna.tf32.f32 %0, %1;" : "=r"(u) : "f"(f));
    return u;
}

__device__ __forceinline__ void mma_tf32(float c[4], const uint32_t a[4],
                                         const uint32_t b[2]) {
    asm volatile(
        "mma.sync.aligned.m16n8k8.row.col.f32.tf32.tf32.f32 "
        "{%0,%1,%2,%3}, {%4,%5,%6,%7}, {%8,%9}, {%0,%1,%2,%3};\n"
        : "+f"(c[0]), "+f"(c[1]), "+f"(c[2]), "+f"(c[3])
        : "r"(a[0]), "r"(a[1]), "r"(a[2]), "r"(a[3]),
          "r"(b[0]), "r"(b[1]));
}

// ---------------------------------------------------------------------------
// Tensor-core GEMM (unchanged from R3 — measured good).
// ---------------------------------------------------------------------------
template<int MODE>
__global__ __launch_bounds__(256)
void gemm_tc(const float* __restrict__ A,
             const float* __restrict__ W,
             const float* __restrict__ bias,
             const float* __restrict__ rope,
             float* __restrict__ out)
{
    __shared__ alignas(16) uint32_t As[128*36];
    __shared__ alignas(16) uint32_t Bs[128*36];

    const int tid  = threadIdx.x;
    const int lane = tid & 31;
    const int w    = tid >> 5;
    const int g    = lane >> 2;
    const int t4   = lane & 3;
    const int wm   = w >> 2;
    const int wn   = w & 3;
    const int m0   = blockIdx.y * 128;
    const int n0   = blockIdx.x * 128;

    float c[4][4][4];
    #pragma unroll
    for (int im = 0; im < 4; im++)
        #pragma unroll
        for (int in = 0; in < 4; in++)
            #pragma unroll
            for (int q = 0; q < 4; q++) c[im][in][q] = 0.f;

    float4 ra[4], rb[4];

    #pragma unroll
    for (int l = 0; l < 4; l++) {
        int e = l*256 + tid, r = e >> 3, c4 = e & 7;
        ra[l] = *(const float4*)(A + (size_t)(m0 + r)*1024 + c4*4);
        rb[l] = *(const float4*)(W + (size_t)(n0 + r)*1024 + c4*4);
    }
    #pragma unroll
    for (int l = 0; l < 4; l++) {
        int e = l*256 + tid, r = e >> 3, c4 = e & 7;
        uint4 pa; pa.x = f2tf32(ra[l].x); pa.y = f2tf32(ra[l].y);
                  pa.z = f2tf32(ra[l].z); pa.w = f2tf32(ra[l].w);
        *(uint4*)&As[r*36 + c4*4] = pa;
        uint4 pb; pb.x = f2tf32(rb[l].x); pb.y = f2tf32(rb[l].y);
                  pb.z = f2tf32(rb[l].z); pb.w = f2tf32(rb[l].w);
        *(uint4*)&Bs[r*36 + c4*4] = pb;
    }
    __syncthreads();

    for (int kt = 0; kt < 1024; kt += 32) {
        const bool more = (kt + 32 < 1024);
        if (more) {
            #pragma unroll
            for (int l = 0; l < 4; l++) {
                int e = l*256 + tid, r = e >> 3, c4 = e & 7;
                ra[l] = *(const float4*)(A + (size_t)(m0 + r)*1024 + kt + 32 + c4*4);
                rb[l] = *(const float4*)(W + (size_t)(n0 + r)*1024 + kt + 32 + c4*4);
            }
        }
        #pragma unroll
        for (int ks = 0; ks < 4; ks++) {
            uint32_t af[4][4], bf[4][2];
            const int kc = ks*8 + t4;
            #pragma unroll
            for (int im = 0; im < 4; im++) {
                int r0 = wm*64 + im*16 + g;
                af[im][0] = As[r0*36       + kc];
                af[im][1] = As[(r0+8)*36   + kc];
                af[im][2] = As[r0*36       + kc + 4];
                af[im][3] = As[(r0+8)*36   + kc + 4];
            }
            #pragma unroll
            for (int in = 0; in < 4; in++) {
                int n = wn*32 + in*8 + g;
                bf[in][0] = Bs[n*36 + kc];
                bf[in][1] = Bs[n*36 + kc + 4];
            }
            #pragma unroll
            for (int im = 0; im < 4; im++)
                #pragma unroll
                for (int in = 0; in < 4; in++)
                    mma_tf32(c[im][in], af[im], bf[in]);
        }
        if (more) {
            __syncthreads();
            #pragma unroll
            for (int l = 0; l < 4; l++) {
                int e = l*256 + tid, r = e >> 3, c4 = e & 7;
                uint4 pa; pa.x = f2tf32(ra[l].x); pa.y = f2tf32(ra[l].y);
                          pa.z = f2tf32(ra[l].z); pa.w = f2tf32(ra[l].w);
                *(uint4*)&As[r*36 + c4*4] = pa;
                uint4 pb; pb.x = f2tf32(rb[l].x); pb.y = f2tf32(rb[l].y);
                          pb.z = f2tf32(rb[l].z); pb.w = f2tf32(rb[l].w);
                *(uint4*)&Bs[r*36 + c4*4] = pb;
            }
            __syncthreads();
        }
    }

    #pragma unroll
    for (int im = 0; im < 4; im++) {
        #pragma unroll
        for (int rh = 0; rh < 2; rh++) {
            int m  = m0 + wm*64 + im*16 + g + rh*8;
            int b  = m >> 11;
            int tt = m & 2047;
            #pragma unroll
            for (int in = 0; in < 4; in++) {
                int n = n0 + wn*32 + in*8 + 2*t4;
                float v0 = c[im][in][rh*2 + 0];
                float v1 = c[im][in][rh*2 + 1];
                if (MODE != 0) { v0 += bias[n]; v1 += bias[n+1]; }
                if (MODE == 1) {
                    int i0 = (n & 63) >> 1;
                    float cs = rope[((size_t)tt*32 + i0)*2 + 0];
                    float sn = rope[((size_t)tt*32 + i0)*2 + 1];
                    float nv0 = cs*v0 - sn*v1;
                    float nv1 = sn*v0 + cs*v1;
                    v0 = nv0; v1 = nv1;
                }
                if (MODE == 0) {
                    *(float2*)(out + (size_t)m*1024 + n) = make_float2(v0, v1);
                } else {
                    int h = n >> 6, hd = n & 63;
                    *(float2*)(out + (((size_t)(b*NHH + h))*TT + tt)*HSS + hd) =
                        make_float2(v0, v1);
                }
            }
        }
    }
}

// ---------------------------------------------------------------------------
// MMA flash attention. grid = (32 qtiles, 32 bh), 128 threads (4 warps).
// Warp w owns q-rows [16w, 16w+16). S/O accumulators in registers.
// A-operands (Q, P): smem stride 76 -> conflict-free (12g+t4 pattern).
// B-operands (K, V): smem stride 72 -> conflict-free (8t4+g pattern).
// Masked / non-causal scores SET to exactly -1e10 (reference semantics);
// fully-masked rows extended uniformly over future tiles via 1/0 P MMA.
// ---------------------------------------------------------------------------
#define ASTR 76
#define BSTR 72

__global__ __launch_bounds__(128)
void attn_mma(const float* __restrict__ Q,
              const float* __restrict__ K,
              const float* __restrict__ V,
              const int* __restrict__ masks,
              float* __restrict__ Y)
{
    extern __shared__ uint32_t sm[];
    uint32_t* Ks = sm;                       // [64][72]
    uint32_t* Vs = sm + 64*BSTR;             // [64][72]
    uint32_t* Qs = sm + 2*64*BSTR;           // [64][76]
    uint32_t* Ps = Qs + 64*ASTR;             // [64][76]
    float*    bm = (float*)(Ps + 64*ASTR);   // [64]
    __shared__ int s_any;

    const int tid  = threadIdx.x;
    const int w    = tid >> 5;
    const int lane = tid & 31;
    const int g    = lane >> 2;
    const int t4   = lane & 3;
    const int bh   = blockIdx.y;
    const int b    = bh >> 4;
    const int h    = bh & 15;
    const int qt   = blockIdx.x;
    const int q0   = qt * 64;
    const float* Qb = Q + (size_t)bh*TT*HSS;
    const float* Kb = K + (size_t)bh*TT*HSS;
    const float* Vb = V + (size_t)bh*TT*HSS;

    // load Q tile -> tf32 smem (stride 76, scalar stores)
    #pragma unroll
    for (int l = 0; l < 8; l++) {
        int e = l*128 + tid, r = e >> 4, c4 = e & 15;
        float4 v = *(const float4*)(Qb + (size_t)(q0 + r)*HSS + c4*4);
        Qs[r*ASTR + c4*4 + 0] = f2tf32(v.x);
        Qs[r*ASTR + c4*4 + 1] = f2tf32(v.y);
        Qs[r*ASTR + c4*4 + 2] = f2tf32(v.z);
        Qs[r*ASTR + c4*4 + 3] = f2tf32(v.w);
    }

    const int qr0 = q0 + w*16 + g;      // this thread's row pair
    const int qr1 = qr0 + 8;
    const int prow0 = (w*16 + g)*ASTR;
    const int prow1 = (w*16 + g + 8)*ASTR;

    float oc[8][4];
    #pragma unroll
    for (int n = 0; n < 8; n++)
        #pragma unroll
        for (int q = 0; q < 4; q++) oc[n][q] = 0.f;
    float mrun0 = -1e30f, mrun1 = -1e30f;
    float l0 = 0.f, l1 = 0.f;

    const int nkt = qt + 1;
    for (int j = 0; j < nkt; j++) {
        __syncthreads();
        const int kbase = j*64;
        #pragma unroll
        for (int l = 0; l < 8; l++) {
            int e = l*128 + tid, r = e >> 4, c4 = e & 15;
            float4 kv = *(const float4*)(Kb + (size_t)(kbase + r)*HSS + c4*4);
            uint4 uk; uk.x = f2tf32(kv.x); uk.y = f2tf32(kv.y);
                      uk.z = f2tf32(kv.z); uk.w = f2tf32(kv.w);
            *(uint4*)&Ks[r*BSTR + c4*4] = uk;
            float4 vv = *(const float4*)(Vb + (size_t)(kbase + r)*HSS + c4*4);
            uint4 uv; uv.x = f2tf32(vv.x); uv.y = f2tf32(vv.y);
                      uv.z = f2tf32(vv.z); uv.w = f2tf32(vv.w);
            *(uint4*)&Vs[r*BSTR + c4*4] = uv;
        }
        if (tid < 64) bm[tid] = (masks[b*TT + kbase + tid] != 0) ? 1.f : 0.f;
        __syncthreads();

        // ---- S = Q K^T (16x64 strip per warp) ----
        float sc[8][4];
        #pragma unroll
        for (int n = 0; n < 8; n++)
            #pragma unroll
            for (int q = 0; q < 4; q++) sc[n][q] = 0.f;
        #pragma unroll
        for (int ks = 0; ks < 8; ks++) {
            uint32_t a[4];
            a[0] = Qs[prow0 + ks*8 + t4];
            a[1] = Qs[prow1 + ks*8 + t4];
            a[2] = Qs[prow0 + ks*8 + t4 + 4];
            a[3] = Qs[prow1 + ks*8 + t4 + 4];
            #pragma unroll
            for (int n = 0; n < 8; n++) {
                uint32_t bb[2];
                bb[0] = Ks[(n*8 + g)*BSTR + ks*8 + t4];
                bb[1] = Ks[(n*8 + g)*BSTR + ks*8 + t4 + 4];
                mma_tf32(sc[n], a, bb);
            }
        }

        // ---- scale + causal + pad mask (exact set to -1e10) ----
        float mx0 = -1e30f, mx1 = -1e30f;
        #pragma unroll
        for (int n = 0; n < 8; n++) {
            int c0 = kbase + n*8 + 2*t4;
            int c1 = c0 + 1;
            float b0 = bm[n*8 + 2*t4];
            float b1 = bm[n*8 + 2*t4 + 1];
            float s00 = (c0 > qr0 || b0 != 0.f) ? -1e10f : sc[n][0]*0.125f;
            float s01 = (c1 > qr0 || b1 != 0.f) ? -1e10f : sc[n][1]*0.125f;
            float s10 = (c0 > qr1 || b0 != 0.f) ? -1e10f : sc[n][2]*0.125f;
            float s11 = (c1 > qr1 || b1 != 0.f) ? -1e10f : sc[n][3]*0.125f;
            sc[n][0] = s00; sc[n][1] = s01; sc[n][2] = s10; sc[n][3] = s11;
            mx0 = fmaxf(mx0, fmaxf(s00, s01));
            mx1 = fmaxf(mx1, fmaxf(s10, s11));
        }
        mx0 = fmaxf(mx0, __shfl_xor_sync(0xffffffffu, mx0, 1));
        mx0 = fmaxf(mx0, __shfl_xor_sync(0xffffffffu, mx0, 2));
        mx1 = fmaxf(mx1, __shfl_xor_sync(0xffffffffu, mx1, 1));
        mx1 = fmaxf(mx1, __shfl_xor_sync(0xffffffffu, mx1, 2));

        float mnew0 = fmaxf(mrun0, mx0);
        float mnew1 = fmaxf(mrun1, mx1);
        float corr0 = __expf(mrun0 - mnew0);
        float corr1 = __expf(mrun1 - mnew1);
        mrun0 = mnew0; mrun1 = mnew1;

        float ps0 = 0.f, ps1 = 0.f;
        #pragma unroll
        for (int n = 0; n < 8; n++) {
            float p00 = __expf(sc[n][0] - mnew0);
            float p01 = __expf(sc[n][1] - mnew0);
            float p10 = __expf(sc[n][2] - mnew1);
            float p11 = __expf(sc[n][3] - mnew1);
            ps0 += p00 + p01;
            ps1 += p10 + p11;
            uint2 u0; u0.x = f2tf32(p00); u0.y = f2tf32(p01);
            *(uint2*)&Ps[prow0 + n*8 + 2*t4] = u0;
            uint2 u1; u1.x = f2tf32(p10); u1.y = f2tf32(p11);
            *(uint2*)&Ps[prow1 + n*8 + 2*t4] = u1;
        }
        ps0 += __shfl_xor_sync(0xffffffffu, ps0, 1);
        ps0 += __shfl_xor_sync(0xffffffffu, ps0, 2);
        ps1 += __shfl_xor_sync(0xffffffffu, ps1, 1);
        ps1 += __shfl_xor_sync(0xffffffffu, ps1, 2);
        l0 = l0*corr0 + ps0;
        l1 = l1*corr1 + ps1;

        #pragma unroll
        for (int n = 0; n < 8; n++) {
            oc[n][0] *= corr0; oc[n][1] *= corr0;
            oc[n][2] *= corr1; oc[n][3] *= corr1;
        }
        __syncwarp();

        // ---- O += P V ----
        #pragma unroll
        for (int ks = 0; ks < 8; ks++) {
            uint32_t a[4];
            a[0] = Ps[prow0 + ks*8 + t4];
            a[1] = Ps[prow1 + ks*8 + t4];
            a[2] = Ps[prow0 + ks*8 + t4 + 4];
            a[3] = Ps[prow1 + ks*8 + t4 + 4];
            #pragma unroll
            for (int n = 0; n < 8; n++) {
                uint32_t bb[2];
                bb[0] = Vs[(ks*8 + t4    )*BSTR + n*8 + g];
                bb[1] = Vs[(ks*8 + t4 + 4)*BSTR + n*8 + g];
                mma_tf32(oc[n], a, bb);
            }
        }
    }

    // ---- degenerate rows: uniform weight over future tiles ----
    bool dg0 = mrun0 < -9.0e9f;
    bool dg1 = mrun1 < -9.0e9f;
    if (tid == 0) s_any = 0;
    __syncthreads();
    if (dg0 || dg1) s_any = 1;
    __syncthreads();
    if (s_any) {
        uint32_t one = 0x3F800000u;
        #pragma unroll
        for (int n = 0; n < 8; n++) {
            uint2 u0; u0.x = dg0 ? one : 0u; u0.y = dg0 ? one : 0u;
            *(uint2*)&Ps[prow0 + n*8 + 2*t4] = u0;
            uint2 u1; u1.x = dg1 ? one : 0u; u1.y = dg1 ? one : 0u;
            *(uint2*)&Ps[prow1 + n*8 + 2*t4] = u1;
        }
        __syncwarp();
        for (int j = nkt; j < TT/64; j++) {
            __syncthreads();
            #pragma unroll
            for (int l = 0; l < 8; l++) {
                int e = l*128 + tid, r = e >> 4, c4 = e & 15;
                float4 vv = *(const float4*)(Vb + (size_t)(j*64 + r)*HSS + c4*4);
                uint4 uv; uv.x = f2tf32(vv.x); uv.y = f2tf32(vv.y);
                          uv.z = f2tf32(vv.z); uv.w = f2tf32(vv.w);
                *(uint4*)&Vs[r*BSTR + c4*4] = uv;
            }
            __syncthreads();
            #pragma unroll
            for (int ks = 0; ks < 8; ks++) {
                uint32_t a[4];
                a[0] = Ps[prow0 + ks*8 + t4];
                a[1] = Ps[prow1 + ks*8 + t4];
                a[2] = Ps[prow0 + ks*8 + t4 + 4];
                a[3] = Ps[prow1 + ks*8 + t4 + 4];
                #pragma unroll
                for (int n = 0; n < 8; n++) {
                    uint32_t bb[2];
                    bb[0] = Vs[(ks*8 + t4    )*BSTR + n*8 + g];
                    bb[1] = Vs[(ks*8 + t4 + 4)*BSTR + n*8 + g];
                    mma_tf32(oc[n], a, bb);
                }
            }
        }
        float add = 64.f * (TT/64 - nkt);
        if (dg0) l0 += add;
        if (dg1) l1 += add;
    }

    // ---- normalize + store ----
    float inv0 = 1.f / l0;
    float inv1 = 1.f / l1;
    int t0 = q0 + w*16 + g;
    float* y0 = Y + ((size_t)(b*TT + t0))*HH + h*HSS;
    float* y1 = Y + ((size_t)(b*TT + t0 + 8))*HH + h*HSS;
    #pragma unroll
    for (int n = 0; n < 8; n++) {
        *(float2*)(y0 + n*8 + 2*t4) =
            make_float2(oc[n][0]*inv0, oc[n][1]*inv0);
        *(float2*)(y1 + n*8 + 2*t4) =
            make_float2(oc[n][2]*inv1, oc[n][3]*inv1);
    }
}

// ---------------------------------------------------------------------------
extern "C" void kernel_launch(void* const* d_in, const int* in_sizes, int n_in,
                              void* d_out, int out_size)
{
    const float* x     = (const float*)d_in[0];
    const int*   masks = (const int*)  d_in[1];
    const float* Wq    = (const float*)d_in[2];
    const float* bq    = (const float*)d_in[3];
    const float* Wk    = (const float*)d_in[4];
    const float* bk    = (const float*)d_in[5];
    const float* Wv    = (const float*)d_in[6];
    const float* bv    = (const float*)d_in[7];
    const float* Wo    = (const float*)d_in[8];
    const float* rope  = (const float*)d_in[9];
    float* out = (float*)d_out;

    float *Qp, *Kp, *Vp, *Yp;
    cudaGetSymbolAddress((void**)&Qp, g_Q);
    cudaGetSymbolAddress((void**)&Kp, g_K);
    cudaGetSymbolAddress((void**)&Vp, g_V);
    cudaGetSymbolAddress((void**)&Yp, g_Y);

    const int attn_smem = (2*64*BSTR + 2*64*ASTR + 64) * (int)sizeof(uint32_t);
    cudaFuncSetAttribute(attn_mma,
                         cudaFuncAttributeMaxDynamicSharedMemorySize, attn_smem);

    dim3 gb(8, 32), tb(256);
    gemm_tc<1><<<gb, tb>>>(x, Wq, bq, rope, Qp);
    gemm_tc<1><<<gb, tb>>>(x, Wk, bk, rope, Kp);
    gemm_tc<2><<<gb, tb>>>(x, Wv, bv, nullptr, Vp);

    attn_mma<<<dim3(TT/64, BB*NHH), 128, attn_smem>>>(Qp, Kp, Vp, masks, Yp);

    gemm_tc<0><<<gb, tb>>>(Yp, Wo, nullptr, nullptr, out);
}